// round 12
// baseline (speedup 1.0000x reference)
#include <cuda_runtime.h>
#include <cuda_bf16.h>
#include <cstdint>
#include <math.h>

#define T_TOK 16384
#define HDIM  1024
#define FDIM  4096
#define NEXP  8
#define NSLOT (T_TOK * 2)

constexpr int BM = 128, BN = 128, BK = 32;
constexpr int LDA = 40;   // padded: 16B-chunk phases conflict-free for ldmatrix
constexpr int LDB = 136;
constexpr int SA_ELEMS = BM * LDA;   // per (stage,half)
constexpr int SB_ELEMS = BK * LDB;
constexpr int SMEM_BYTES = (4 * SA_ELEMS + 4 * SB_ELEMS) * 2;  // 75776

// ---------- device scratch (static globals: allocation-guard safe) ----------
__device__ __nv_bfloat16 g_x_hi[(size_t)T_TOK * HDIM];
__device__ __nv_bfloat16 g_x_lo[(size_t)T_TOK * HDIM];
__device__ __nv_bfloat16 g_w1_hi[(size_t)NEXP * HDIM * FDIM];
__device__ __nv_bfloat16 g_w1_lo[(size_t)NEXP * HDIM * FDIM];
__device__ __nv_bfloat16 g_w2_hi[(size_t)NEXP * FDIM * HDIM];
__device__ __nv_bfloat16 g_w2_lo[(size_t)NEXP * FDIM * HDIM];
__device__ __nv_bfloat16 g_h_hi[(size_t)NSLOT * FDIM];
__device__ __nv_bfloat16 g_h_lo[(size_t)NSLOT * FDIM];
__device__ float         g_yy[(size_t)NSLOT * HDIM];

__device__ int   g_eid[T_TOK * 2];
__device__ float g_gate[T_TOK * 2];
__device__ int   g_counts[NEXP];
__device__ int   g_offsets[NEXP];
__device__ int   g_cursor[NEXP];
__device__ int   g_rows[NSLOT];
__device__ float g_rowgate[NSLOT];
__device__ int   g_slot[T_TOK * 2];

// ---------- PTX helpers ----------
__device__ __forceinline__ uint32_t smem_u32(const void* p) {
    return (uint32_t)__cvta_generic_to_shared(p);
}
__device__ __forceinline__ void cpa16(uint32_t dst, const void* src) {
    asm volatile("cp.async.cg.shared.global [%0], [%1], 16;\n" :: "r"(dst), "l"(src));
}
__device__ __forceinline__ void ldsm_x4(uint32_t* r, uint32_t a) {
    asm volatile("ldmatrix.sync.aligned.m8n8.x4.shared.b16 {%0,%1,%2,%3}, [%4];\n"
                 : "=r"(r[0]), "=r"(r[1]), "=r"(r[2]), "=r"(r[3]) : "r"(a));
}
__device__ __forceinline__ void ldsm_x4t(uint32_t* r, uint32_t a) {
    asm volatile("ldmatrix.sync.aligned.m8n8.x4.trans.shared.b16 {%0,%1,%2,%3}, [%4];\n"
                 : "=r"(r[0]), "=r"(r[1]), "=r"(r[2]), "=r"(r[3]) : "r"(a));
}
__device__ __forceinline__ void mma_bf16(float* c, const uint32_t* a, const uint32_t* b) {
    asm volatile("mma.sync.aligned.m16n8k16.row.col.f32.bf16.bf16.f32 "
                 "{%0,%1,%2,%3}, {%4,%5,%6,%7}, {%8,%9}, {%0,%1,%2,%3};\n"
                 : "+f"(c[0]), "+f"(c[1]), "+f"(c[2]), "+f"(c[3])
                 : "r"(a[0]), "r"(a[1]), "r"(a[2]), "r"(a[3]), "r"(b[0]), "r"(b[1]));
}

// ---------- setup ----------
__global__ void k_split(const float* __restrict__ in, int n, int which) {
    int i = blockIdx.x * blockDim.x + threadIdx.x;
    if (i >= n) return;
    float v = in[i];
    __nv_bfloat16 h = __float2bfloat16(v);
    __nv_bfloat16 l = __float2bfloat16(v - __bfloat162float(h));
    if (which == 0)      { g_x_hi[i] = h;  g_x_lo[i] = l; }
    else if (which == 1) { g_w1_hi[i] = h; g_w1_lo[i] = l; }
    else                 { g_w2_hi[i] = h; g_w2_lo[i] = l; }
}

__global__ void k_init() {
    if (threadIdx.x < NEXP) { g_counts[threadIdx.x] = 0; g_cursor[threadIdx.x] = 0; }
}

// one warp per token
__global__ void __launch_bounds__(256) k_router(const float* __restrict__ x,
                                                const float* __restrict__ Wg) {
    int t = blockIdx.x * 8 + (threadIdx.x >> 5);
    int lane = threadIdx.x & 31;
    float acc[NEXP];
#pragma unroll
    for (int e = 0; e < NEXP; e++) acc[e] = 0.0f;
    const float* xr = x + (size_t)t * HDIM;
#pragma unroll 4
    for (int j = 0; j < HDIM / 32; j++) {
        int h = j * 32 + lane;
        float xv = xr[h];
        const float4* wg = reinterpret_cast<const float4*>(Wg + (size_t)h * NEXP);
        float4 w0 = wg[0], w1 = wg[1];
        acc[0] += xv * w0.x; acc[1] += xv * w0.y; acc[2] += xv * w0.z; acc[3] += xv * w0.w;
        acc[4] += xv * w1.x; acc[5] += xv * w1.y; acc[6] += xv * w1.z; acc[7] += xv * w1.w;
    }
#pragma unroll
    for (int o = 16; o > 0; o >>= 1)
#pragma unroll
        for (int e = 0; e < NEXP; e++)
            acc[e] += __shfl_xor_sync(0xffffffffu, acc[e], o);
    if (lane == 0) {
        float m = acc[0];
#pragma unroll
        for (int e = 1; e < NEXP; e++) m = fmaxf(m, acc[e]);
        float ex[NEXP];
#pragma unroll
        for (int e = 0; e < NEXP; e++) ex[e] = expf(acc[e] - m);
        int i1 = 0;
#pragma unroll
        for (int e = 1; e < NEXP; e++) if (ex[e] > ex[i1]) i1 = e;
        int i2 = (i1 == 0) ? 1 : 0;
#pragma unroll
        for (int e = 0; e < NEXP; e++) if (e != i1 && ex[e] > ex[i2]) i2 = e;
        float s2 = ex[i1] + ex[i2];
        g_eid[2 * t]     = i1; g_gate[2 * t]     = ex[i1] / s2;
        g_eid[2 * t + 1] = i2; g_gate[2 * t + 1] = ex[i2] / s2;
        atomicAdd(&g_counts[i1], 1);
        atomicAdd(&g_counts[i2], 1);
    }
}

__global__ void k_scan() {
    if (threadIdx.x == 0) {
        int s = 0;
        for (int e = 0; e < NEXP; e++) { g_offsets[e] = s; s += g_counts[e]; }
    }
}

__global__ void k_scatter() {
    int t = blockIdx.x * blockDim.x + threadIdx.x;
    if (t >= T_TOK) return;
#pragma unroll
    for (int k = 0; k < 2; k++) {
        int e = g_eid[2 * t + k];
        int pos = g_offsets[e] + atomicAdd(&g_cursor[e], 1);
        g_rows[pos] = t;
        g_rowgate[pos] = g_gate[2 * t + k];
        g_slot[2 * t + k] = pos;
    }
}

// ---------- grouped GEMM, split-bf16 (3 MMAs) ----------
template <int KTOT, int NLD, bool IS_G1>
__global__ void __launch_bounds__(256) k_gemm() {
    const int e = blockIdx.z;
    const int Mcnt = g_counts[e];
    const int mBase = blockIdx.y * BM;
    if (mBase >= Mcnt) return;
    const int off = g_offsets[e];
    const int nBase = blockIdx.x * BN;
    const int tid = threadIdx.x;

    extern __shared__ __nv_bfloat16 sm[];
    uint32_t sA0 = smem_u32(sm);
    uint32_t sB0 = sA0 + 4 * SA_ELEMS * 2;
    uint32_t sAa[2][2], sBa[2][2];
#pragma unroll
    for (int st = 0; st < 2; st++)
#pragma unroll
        for (int hf = 0; hf < 2; hf++) {
            sAa[st][hf] = sA0 + (st * 2 + hf) * SA_ELEMS * 2;
            sBa[st][hf] = sB0 + (st * 2 + hf) * SB_ELEMS * 2;
        }

    // per-thread cp.async assignments
    const __nv_bfloat16 *aHi[2], *aLo[2], *bHi[2], *bLo[2];
    uint32_t aD[2], bD[2];
#pragma unroll
    for (int i = 0; i < 2; i++) {
        int id = tid * 2 + i;
        int r = id >> 2, cc = id & 3;            // A: 128 rows x 4 chunks
        int m = mBase + r; if (m >= Mcnt) m = Mcnt - 1;
        if (IS_G1) {
            size_t ro = (size_t)g_rows[off + m] * HDIM + cc * 8;
            aHi[i] = g_x_hi + ro; aLo[i] = g_x_lo + ro;
        } else {
            size_t ro = (size_t)(off + m) * FDIM + cc * 8;
            aHi[i] = g_h_hi + ro; aLo[i] = g_h_lo + ro;
        }
        aD[i] = (uint32_t)((r * LDA + cc * 8) * 2);

        int k = id >> 4, c2 = id & 15;           // B: 32 k-rows x 16 chunks
        size_t bo = (size_t)e * KTOT * NLD + (size_t)k * NLD + nBase + c2 * 8;
        if (IS_G1) { bHi[i] = g_w1_hi + bo; bLo[i] = g_w1_lo + bo; }
        else       { bHi[i] = g_w2_hi + bo; bLo[i] = g_w2_lo + bo; }
        bD[i] = (uint32_t)((k * LDB + c2 * 8) * 2);
    }

    auto loadStage = [&](int st, int kt) {
        size_t ka = (size_t)kt * BK;
        size_t kb = (size_t)kt * BK * NLD;
#pragma unroll
        for (int i = 0; i < 2; i++) {
            cpa16(sAa[st][0] + aD[i], aHi[i] + ka);
            cpa16(sAa[st][1] + aD[i], aLo[i] + ka);
            cpa16(sBa[st][0] + bD[i], bHi[i] + kb);
            cpa16(sBa[st][1] + bD[i], bLo[i] + kb);
        }
        asm volatile("cp.async.commit_group;\n" ::);
    };

    const int lane = tid & 31, warp = tid >> 5;
    const int wm = warp >> 2, wn = warp & 3;     // warp tile 64x32 at (wm*64, wn*32)
    const int aRow = wm * 64 + (lane & 15);
    const int aCol = (lane >> 4) * 8;
    const int bRow = (lane & 15);
    const int bCol = wn * 32 + (lane >> 4) * 8;

    float acc[4][4][4];
#pragma unroll
    for (int a = 0; a < 4; a++)
#pragma unroll
        for (int b = 0; b < 4; b++)
#pragma unroll
            for (int c = 0; c < 4; c++) acc[a][b][c] = 0.0f;

    const int KT = KTOT / BK;
    loadStage(0, 0);
    for (int kt = 0; kt < KT; kt++) {
        const int st = kt & 1;
        if (kt + 1 < KT) {
            loadStage((kt + 1) & 1, kt + 1);
            asm volatile("cp.async.wait_group 1;\n" ::);
        } else {
            asm volatile("cp.async.wait_group 0;\n" ::);
        }
        __syncthreads();
#pragma unroll
        for (int k16 = 0; k16 < 2; k16++) {
            uint32_t ah[4][4], al[4][4], bh[2][4], bl[2][4];
#pragma unroll
            for (int mi = 0; mi < 4; mi++) {
                uint32_t o = ((aRow + mi * 16) * LDA + aCol + k16 * 16) * 2;
                ldsm_x4(ah[mi], sAa[st][0] + o);
                ldsm_x4(al[mi], sAa[st][1] + o);
            }
#pragma unroll
            for (int np = 0; np < 2; np++) {
                uint32_t o = ((bRow + k16 * 16) * LDB + bCol + np * 16) * 2;
                ldsm_x4t(bh[np], sBa[st][0] + o);
                ldsm_x4t(bl[np], sBa[st][1] + o);
            }
#pragma unroll
            for (int mi = 0; mi < 4; mi++)
#pragma unroll
                for (int ni = 0; ni < 4; ni++) {
                    const uint32_t* Bh = &bh[ni >> 1][(ni & 1) * 2];
                    const uint32_t* Bl = &bl[ni >> 1][(ni & 1) * 2];
                    mma_bf16(acc[mi][ni], ah[mi], Bh);
                    mma_bf16(acc[mi][ni], ah[mi], Bl);
                    mma_bf16(acc[mi][ni], al[mi], Bh);
                }
        }
        __syncthreads();
    }

    // epilogue
    const int og = lane >> 2, otg = lane & 3;
#pragma unroll
    for (int mi = 0; mi < 4; mi++)
#pragma unroll
        for (int hh = 0; hh < 2; hh++) {
            int m = mBase + wm * 64 + mi * 16 + og + hh * 8;
            if (m < Mcnt) {
                int slot = off + m;
                if (IS_G1) {
#pragma unroll
                    for (int ni = 0; ni < 4; ni++) {
                        int n = nBase + wn * 32 + ni * 8 + otg * 2;
                        float v0 = acc[mi][ni][hh * 2];
                        float v1 = acc[mi][ni][hh * 2 + 1];
                        v0 = v0 / (1.0f + __expf(-v0));
                        v1 = v1 / (1.0f + __expf(-v1));
                        __nv_bfloat16 h0 = __float2bfloat16(v0);
                        __nv_bfloat16 h1 = __float2bfloat16(v1);
                        __nv_bfloat16 l0 = __float2bfloat16(v0 - __bfloat162float(h0));
                        __nv_bfloat16 l1 = __float2bfloat16(v1 - __bfloat162float(h1));
                        size_t o = (size_t)slot * FDIM + n;
                        *reinterpret_cast<__nv_bfloat162*>(&g_h_hi[o]) = __halves2bfloat162(h0, h1);
                        *reinterpret_cast<__nv_bfloat162*>(&g_h_lo[o]) = __halves2bfloat162(l0, l1);
                    }
                } else {
                    float gate = g_rowgate[slot];
#pragma unroll
                    for (int ni = 0; ni < 4; ni++) {
                        int n = nBase + wn * 32 + ni * 8 + otg * 2;
                        float2 w;
                        w.x = gate * acc[mi][ni][hh * 2];
                        w.y = gate * acc[mi][ni][hh * 2 + 1];
                        *reinterpret_cast<float2*>(&g_yy[(size_t)slot * HDIM + n]) = w;
                    }
                }
            }
        }
}

__global__ void k_combine(float* __restrict__ out) {
    int idx = blockIdx.x * blockDim.x + threadIdx.x;
    const int W = HDIM / 4;
    if (idx >= T_TOK * W) return;
    int t = idx / W, j = idx % W;
    const float4* yy = reinterpret_cast<const float4*>(g_yy);
    float4 a = yy[(size_t)g_slot[2 * t] * W + j];
    float4 b = yy[(size_t)g_slot[2 * t + 1] * W + j];
    float4 r;
    r.x = a.x + b.x; r.y = a.y + b.y; r.z = a.z + b.z; r.w = a.w + b.w;
    reinterpret_cast<float4*>(out)[idx] = r;
}

extern "C" void kernel_launch(void* const* d_in, const int* in_sizes, int n_in,
                              void* d_out, int out_size) {
    const float* x  = (const float*)d_in[0];
    const float* Wg = (const float*)d_in[1];
    const float* w1 = (const float*)d_in[2];
    const float* w2 = (const float*)d_in[3];
    float* out = (float*)d_out;

    cudaFuncSetAttribute(k_gemm<HDIM, FDIM, true>,
                         cudaFuncAttributeMaxDynamicSharedMemorySize, SMEM_BYTES);
    cudaFuncSetAttribute(k_gemm<FDIM, HDIM, false>,
                         cudaFuncAttributeMaxDynamicSharedMemorySize, SMEM_BYTES);

    k_init<<<1, 32>>>();
    int nx = T_TOK * HDIM;
    k_split<<<(nx + 255) / 256, 256>>>(x, nx, 0);
    int nw = NEXP * HDIM * FDIM;
    k_split<<<(nw + 255) / 256, 256>>>(w1, nw, 1);
    k_split<<<(nw + 255) / 256, 256>>>(w2, nw, 2);
    k_router<<<T_TOK / 8, 256>>>(x, Wg);
    k_scan<<<1, 1>>>();
    k_scatter<<<(T_TOK + 255) / 256, 256>>>();
    k_gemm<HDIM, FDIM, true><<<dim3(FDIM / BN, 64, NEXP), 256, SMEM_BYTES>>>();
    k_gemm<FDIM, HDIM, false><<<dim3(HDIM / BN, 64, NEXP), 256, SMEM_BYTES>>>();
    k_combine<<<(T_TOK * (HDIM / 4) + 255) / 256, 256>>>(out);
}